// round 2
// baseline (speedup 1.0000x reference)
#include <cuda_runtime.h>
#include <cstdint>

// Problem constants
#define CCH    384
#define NPIX   1024          // 32*32
#define NIMG   16            // only first n=16 rows matter
#define KTOP   20
#define PTOT   96
#define NREM   76            // P - K
#define NUNSEL 1004          // 1024 - 20
#define NCHUNK 24
#define CHPER  16            // 384 / 24
#define NPERMBLK 16
#define ELEM_PER_PB 63       // 16*63 = 1008 >= 1004

// Scratch (device globals: no allocation allowed)
__device__ float g_partial[NCHUNK * NIMG * NPIX];   // [chunk][img][pix]
__device__ int   g_invperm[NUNSEL];

__device__ __forceinline__ uint32_t rotl32(uint32_t x, int d) {
    return (x << d) | (x >> (32 - d));
}

// Threefry-2x32, 20 rounds (matches JAX threefry2x32_p)
__device__ __forceinline__ void threefry2x32(uint32_t k0, uint32_t k1,
                                             uint32_t x0, uint32_t x1,
                                             uint32_t& o0, uint32_t& o1) {
    uint32_t k2 = k0 ^ k1 ^ 0x1BD11BDAu;
#define TF_RND(r) { x0 += x1; x1 = rotl32(x1, (r)); x1 ^= x0; }
    x0 += k0; x1 += k1;
    TF_RND(13) TF_RND(15) TF_RND(26) TF_RND(6)
    x0 += k1; x1 += k2 + 1u;
    TF_RND(17) TF_RND(29) TF_RND(16) TF_RND(24)
    x0 += k2; x1 += k0 + 2u;
    TF_RND(13) TF_RND(15) TF_RND(26) TF_RND(6)
    x0 += k0; x1 += k1 + 3u;
    TF_RND(17) TF_RND(29) TF_RND(16) TF_RND(24)
    x0 += k1; x1 += k2 + 4u;
    TF_RND(13) TF_RND(15) TF_RND(26) TF_RND(6)
    x0 += k2; x1 += k0 + 5u;
#undef TF_RND
    o0 = x0; o1 = x1;
}

// ---------------------------------------------------------------------------
// Kernel A: blocks [0, NPERMBLK) compute the JAX permutation inverse map;
//           blocks [NPERMBLK, NPERMBLK + NCHUNK*NIMG) compute fused
//           depthwise-3x3 + pointwise partial sums.
// ---------------------------------------------------------------------------
__global__ __launch_bounds__(256)
void patch_vote_kA(const float* __restrict__ feature,
                   const float* __restrict__ dww,
                   const float* __restrict__ pww) {
    int tid = threadIdx.x;

    if (blockIdx.x < NPERMBLK) {
        // ---- permutation block ----
        __shared__ __align__(16) uint32_t bits[NUNSEL];   // 1004 = 251 * 4
        // subkey = second key of fold-like split of key (0, 42)
        uint32_t s0, s1;
        threefry2x32(0u, 42u, 0u, 1u, s0, s1);
        for (int i = tid; i < NUNSEL; i += 256) {
            uint32_t b1, b2;
            threefry2x32(s0, s1, 0u, (uint32_t)i, b1, b2);
            bits[i] = b1 ^ b2;      // partitionable 32-bit fold
        }
        __syncthreads();

        int e = tid >> 2, part = tid & 3;
        int idx = blockIdx.x * ELEM_PER_PB + e;
        int rank = 0;
        bool valid = (e < ELEM_PER_PB) && (idx < NUNSEL);
        if (valid) {
            uint32_t bi = bits[idx];
            int q4b = part * 63;
            int q4e = q4b + 63; if (q4e > 251) q4e = 251;
            const uint4* b4 = reinterpret_cast<const uint4*>(bits);
            for (int q4 = q4b; q4 < q4e; q4++) {
                uint4 v = b4[q4];
                int q = q4 * 4;
                rank += (v.x < bi) || (v.x == bi && (q    ) < idx);
                rank += (v.y < bi) || (v.y == bi && (q + 1) < idx);
                rank += (v.z < bi) || (v.z == bi && (q + 2) < idx);
                rank += (v.w < bi) || (v.w == bi && (q + 3) < idx);
            }
        }
        rank += __shfl_xor_sync(0xffffffffu, rank, 1);
        rank += __shfl_xor_sync(0xffffffffu, rank, 2);
        if (valid && part == 0)
            g_invperm[idx] = (rank < NREM) ? rank : -1;
        return;
    }

    // ---- conv block ----
    int id    = blockIdx.x - NPERMBLK;
    int img   = id / NCHUNK;
    int chunk = id - img * NCHUNK;
    int c0    = chunk * CHPER;

    __shared__ float plane[34 * 34];
    for (int i = tid; i < 34 * 34; i += 256) plane[i] = 0.f;

    // 2x2 output tile per thread
    int tx = tid & 15, ty = tid >> 4;
    int px = tx * 2, py = ty * 2;

    float acc00 = 0.f, acc01 = 0.f, acc10 = 0.f, acc11 = 0.f;
    const float* fbase = feature + ((size_t)img * CCH + c0) * NPIX;

    // load-pixel mapping for this thread (float4)
    int lp = tid * 4;
    int ly = lp >> 5, lx = lp & 31;
    float* dst = &plane[(ly + 1) * 34 + lx + 1];

    float4 v = reinterpret_cast<const float4*>(fbase)[tid];   // c = 0 prefetch

    for (int c = 0; c < CHPER; c++) {
        __syncthreads();                 // prev compute done reading plane
        dst[0] = v.x; dst[1] = v.y; dst[2] = v.z; dst[3] = v.w;
        __syncthreads();
        if (c + 1 < CHPER)
            v = reinterpret_cast<const float4*>(fbase + (c + 1) * NPIX)[tid];

        const float* wc = dww + (size_t)(c0 + c) * 9;
        float w0 = __ldg(wc + 0), w1 = __ldg(wc + 1), w2 = __ldg(wc + 2);
        float w3 = __ldg(wc + 3), w4 = __ldg(wc + 4), w5 = __ldg(wc + 5);
        float w6 = __ldg(wc + 6), w7 = __ldg(wc + 7), w8 = __ldg(wc + 8);
        float pwc = __ldg(pww + c0 + c);

        // 4x4 patch: plane rows py..py+3, cols px..px+3
        const float* pr = &plane[py * 34 + px];
        float a00 = pr[0],      a01 = pr[1],      a02 = pr[2],      a03 = pr[3];
        float a10 = pr[34],     a11 = pr[35],     a12 = pr[36],     a13 = pr[37];
        float a20 = pr[68],     a21 = pr[69],     a22 = pr[70],     a23 = pr[71];
        float a30 = pr[102],    a31 = pr[103],    a32 = pr[104],    a33 = pr[105];

        float s00 = w0*a00 + w1*a01 + w2*a02
                  + w3*a10 + w4*a11 + w5*a12
                  + w6*a20 + w7*a21 + w8*a22;
        float s01 = w0*a01 + w1*a02 + w2*a03
                  + w3*a11 + w4*a12 + w5*a13
                  + w6*a21 + w7*a22 + w8*a23;
        float s10 = w0*a10 + w1*a11 + w2*a12
                  + w3*a20 + w4*a21 + w5*a22
                  + w6*a30 + w7*a31 + w8*a32;
        float s11 = w0*a11 + w1*a12 + w2*a13
                  + w3*a21 + w4*a22 + w5*a23
                  + w6*a31 + w7*a32 + w8*a33;

        acc00 = fmaf(pwc, s00, acc00);
        acc01 = fmaf(pwc, s01, acc01);
        acc10 = fmaf(pwc, s10, acc10);
        acc11 = fmaf(pwc, s11, acc11);
    }

    float* outp = g_partial + (size_t)(chunk * NIMG + img) * NPIX;
    outp[ py      * 32 + px    ] = acc00;
    outp[ py      * 32 + px + 1] = acc01;
    outp[(py + 1) * 32 + px    ] = acc10;
    outp[(py + 1) * 32 + px + 1] = acc11;
}

// ---------------------------------------------------------------------------
// Kernel B: per-image deterministic reduce, top-20 (JAX tie semantics),
//           unselected position via ballot prefix, invperm gather,
//           FLOAT32 outputs (test template compares as float32).
// ---------------------------------------------------------------------------
__global__ __launch_bounds__(1024)
void patch_vote_kB(const float* __restrict__ dwb,
                   const float* __restrict__ pww,
                   const float* __restrict__ pwb,
                   float* __restrict__ out) {
    int tid = threadIdx.x;
    int img = blockIdx.x;
    int lane = tid & 31, warp = tid >> 5;

    __shared__ float s_bias;
    __shared__ unsigned long long warpmax[32];
    __shared__ unsigned long long s_winner;
    __shared__ int s_invp[NUNSEL];
    __shared__ int warpcnt[32];

    if (tid < 32) {
        float b = 0.f;
        for (int i = tid; i < CCH; i += 32) b += pww[i] * dwb[i];
        for (int off = 16; off; off >>= 1) b += __shfl_down_sync(0xffffffffu, b, off);
        if (tid == 0) s_bias = b + pwb[0];
    }
    if (tid < NUNSEL) s_invp[tid] = g_invperm[tid];
    __syncthreads();

    // deterministic chunk reduction
    float val = s_bias;
    const float* pp = g_partial + (size_t)img * NPIX + tid;
#pragma unroll
    for (int c = 0; c < NCHUNK; c++) val += pp[(size_t)c * NIMG * NPIX];

    // orderable key: (monotone float bits : 1023 - idx) so max == JAX top_k order
    uint32_t fb = __float_as_uint(val);
    fb = (fb & 0x80000000u) ? ~fb : (fb | 0x80000000u);
    unsigned long long key = ((unsigned long long)fb << 32) | (uint32_t)(NPIX - 1 - tid);

    int myrank = -1;
    for (int r = 0; r < KTOP; r++) {
        unsigned long long k = key;
        for (int off = 16; off; off >>= 1) {
            unsigned long long o = __shfl_down_sync(0xffffffffu, k, off);
            if (o > k) k = o;
        }
        if (lane == 0) warpmax[warp] = k;
        __syncthreads();
        if (warp == 0) {
            unsigned long long k2 = warpmax[lane];
            for (int off = 16; off; off >>= 1) {
                unsigned long long o = __shfl_down_sync(0xffffffffu, k2, off);
                if (o > k2) k2 = o;
            }
            if (lane == 0) s_winner = k2;
        }
        __syncthreads();
        if (key == s_winner) { myrank = r; key = 0ull; }
        // safe: s_winner next written only after the next iteration's barrier
    }

    int X = tid & 31, Y = tid >> 5;
    float xo = (float)(X < 1 ? 1 : (X > 31 ? 31 : X));
    float yo = (float)(Y < 1 ? 1 : (Y > 31 ? 31 : Y));

    float* xout = out;
    float* yout = out + NIMG * PTOT;

    if (myrank >= 0) {
        xout[img * PTOT + myrank] = xo;
        yout[img * PTOT + myrank] = yo;
    }

    bool sel = (myrank >= 0);
    unsigned bal = __ballot_sync(0xffffffffu, sel);
    if (lane == 0) warpcnt[warp] = __popc(bal);
    __syncthreads();
    int before = __popc(bal & ((1u << lane) - 1u));
    for (int w2 = 0; w2 < warp; w2++) before += warpcnt[w2];

    if (!sel) {
        int u = tid - before;           // position among unselected (0..1003)
        int j = s_invp[u];
        if (j >= 0) {
            xout[img * PTOT + KTOP + j] = xo;
            yout[img * PTOT + KTOP + j] = yo;
        }
    }
}

extern "C" void kernel_launch(void* const* d_in, const int* in_sizes, int n_in,
                              void* d_out, int out_size) {
    const float* feature = (const float*)d_in[0];
    const float* dww     = (const float*)d_in[1];
    const float* dwb     = (const float*)d_in[2];
    const float* pww     = (const float*)d_in[3];
    const float* pwb     = (const float*)d_in[4];
    float* out = (float*)d_out;

    patch_vote_kA<<<NPERMBLK + NCHUNK * NIMG, 256>>>(feature, dww, pww);
    patch_vote_kB<<<NIMG, 1024>>>(dwb, pww, pwb, out);
}

// round 3
// speedup vs baseline: 1.0290x; 1.0290x over previous
#include <cuda_runtime.h>
#include <cstdint>

// Problem constants
#define CCH    384
#define NPIX   1024          // 32*32
#define NIMG   16            // only first n=16 rows matter
#define KTOP   20
#define PTOT   96
#define NREM   76            // P - K
#define NUNSEL 1004          // 1024 - 20
#define NCHUNK 24
#define CHPER  16            // 384 / 24
#define NPERMBLK 16
#define ELEM_PER_PB 63       // 16*63 = 1008 >= 1004
#define PLSZ   (34 * 34)

// Scratch (device globals: no allocation allowed)
__device__ float g_partial[NCHUNK * NIMG * NPIX];   // [chunk][img][pix]
__device__ int   g_invperm[NUNSEL];

__device__ __forceinline__ uint32_t rotl32(uint32_t x, int d) {
    return (x << d) | (x >> (32 - d));
}

// Threefry-2x32, 20 rounds (matches JAX threefry2x32_p)
__device__ __forceinline__ void threefry2x32(uint32_t k0, uint32_t k1,
                                             uint32_t x0, uint32_t x1,
                                             uint32_t& o0, uint32_t& o1) {
    uint32_t k2 = k0 ^ k1 ^ 0x1BD11BDAu;
#define TF_RND(r) { x0 += x1; x1 = rotl32(x1, (r)); x1 ^= x0; }
    x0 += k0; x1 += k1;
    TF_RND(13) TF_RND(15) TF_RND(26) TF_RND(6)
    x0 += k1; x1 += k2 + 1u;
    TF_RND(17) TF_RND(29) TF_RND(16) TF_RND(24)
    x0 += k2; x1 += k0 + 2u;
    TF_RND(13) TF_RND(15) TF_RND(26) TF_RND(6)
    x0 += k0; x1 += k1 + 3u;
    TF_RND(17) TF_RND(29) TF_RND(16) TF_RND(24)
    x0 += k1; x1 += k2 + 4u;
    TF_RND(13) TF_RND(15) TF_RND(26) TF_RND(6)
    x0 += k2; x1 += k0 + 5u;
#undef TF_RND
    o0 = x0; o1 = x1;
}

// ---------------------------------------------------------------------------
// Kernel A: blocks [0, NPERMBLK) compute the JAX permutation inverse map;
//           blocks [NPERMBLK, NPERMBLK + NCHUNK*NIMG) compute fused
//           depthwise-3x3 + pointwise partial sums (ping-pong smem planes).
// ---------------------------------------------------------------------------
__global__ __launch_bounds__(256)
void patch_vote_kA(const float* __restrict__ feature,
                   const float* __restrict__ dww,
                   const float* __restrict__ pww) {
    int tid = threadIdx.x;

    if (blockIdx.x < NPERMBLK) {
        // ---- permutation block ----
        __shared__ __align__(16) uint32_t bits[NUNSEL];   // 1004 = 251 * 4
        uint32_t s0, s1;
        threefry2x32(0u, 42u, 0u, 1u, s0, s1);
        for (int i = tid; i < NUNSEL; i += 256) {
            uint32_t b1, b2;
            threefry2x32(s0, s1, 0u, (uint32_t)i, b1, b2);
            bits[i] = b1 ^ b2;      // partitionable 32-bit fold
        }
        __syncthreads();

        int e = tid >> 2, part = tid & 3;
        int idx = blockIdx.x * ELEM_PER_PB + e;
        int rank = 0;
        bool valid = (e < ELEM_PER_PB) && (idx < NUNSEL);
        if (valid) {
            uint32_t bi = bits[idx];
            int q4b = part * 63;
            int q4e = q4b + 63; if (q4e > 251) q4e = 251;
            const uint4* b4 = reinterpret_cast<const uint4*>(bits);
            for (int q4 = q4b; q4 < q4e; q4++) {
                uint4 v = b4[q4];
                int q = q4 * 4;
                rank += (v.x < bi) || (v.x == bi && (q    ) < idx);
                rank += (v.y < bi) || (v.y == bi && (q + 1) < idx);
                rank += (v.z < bi) || (v.z == bi && (q + 2) < idx);
                rank += (v.w < bi) || (v.w == bi && (q + 3) < idx);
            }
        }
        rank += __shfl_xor_sync(0xffffffffu, rank, 1);
        rank += __shfl_xor_sync(0xffffffffu, rank, 2);
        if (valid && part == 0)
            g_invperm[idx] = (rank < NREM) ? rank : -1;
        return;
    }

    // ---- conv block ----
    int id    = blockIdx.x - NPERMBLK;
    int img   = id / NCHUNK;
    int chunk = id - img * NCHUNK;
    int c0    = chunk * CHPER;

    __shared__ float plane[2 * PLSZ];
    for (int i = tid; i < 2 * PLSZ; i += 256) plane[i] = 0.f;

    // 2x2 output tile per thread
    int tx = tid & 15, ty = tid >> 4;
    int px = tx * 2, py = ty * 2;

    float acc00 = 0.f, acc01 = 0.f, acc10 = 0.f, acc11 = 0.f;
    const float4* f4 = reinterpret_cast<const float4*>(
        feature + ((size_t)img * CCH + c0) * NPIX);

    // float4 load -> smem mapping for this thread
    int lp = tid * 4;
    int ly = lp >> 5, lx = lp & 31;
    int dstoff = (ly + 1) * 34 + lx + 1;

    float4 va = f4[tid];                 // channel 0
    __syncthreads();                     // halo zero-init complete
    {
        float* d = plane + dstoff;       // buffer 0
        d[0] = va.x; d[1] = va.y; d[2] = va.z; d[3] = va.w;
    }
    float4 vb = f4[256 + tid];           // channel 1 prefetch
    __syncthreads();                     // plane0 ready

#pragma unroll 4
    for (int c = 0; c < CHPER; c++) {
        const float* curp = plane + (c & 1) * PLSZ;

        if (c + 1 < CHPER) {
            float* d = plane + ((c + 1) & 1) * PLSZ + dstoff;
            d[0] = vb.x; d[1] = vb.y; d[2] = vb.z; d[3] = vb.w;
        }
        if (c + 2 < CHPER)
            vb = f4[(c + 2) * 256 + tid];

        const float* wc = dww + (size_t)(c0 + c) * 9;
        float w0 = __ldg(wc + 0), w1 = __ldg(wc + 1), w2 = __ldg(wc + 2);
        float w3 = __ldg(wc + 3), w4 = __ldg(wc + 4), w5 = __ldg(wc + 5);
        float w6 = __ldg(wc + 6), w7 = __ldg(wc + 7), w8 = __ldg(wc + 8);
        float pwc = __ldg(pww + c0 + c);

        const float* pr = curp + py * 34 + px;
        float a00 = pr[0],   a01 = pr[1],   a02 = pr[2],   a03 = pr[3];
        float a10 = pr[34],  a11 = pr[35],  a12 = pr[36],  a13 = pr[37];
        float a20 = pr[68],  a21 = pr[69],  a22 = pr[70],  a23 = pr[71];
        float a30 = pr[102], a31 = pr[103], a32 = pr[104], a33 = pr[105];

        float s00 = w0*a00 + w1*a01 + w2*a02
                  + w3*a10 + w4*a11 + w5*a12
                  + w6*a20 + w7*a21 + w8*a22;
        float s01 = w0*a01 + w1*a02 + w2*a03
                  + w3*a11 + w4*a12 + w5*a13
                  + w6*a21 + w7*a22 + w8*a23;
        float s10 = w0*a10 + w1*a11 + w2*a12
                  + w3*a20 + w4*a21 + w5*a22
                  + w6*a30 + w7*a31 + w8*a32;
        float s11 = w0*a11 + w1*a12 + w2*a13
                  + w3*a21 + w4*a22 + w5*a23
                  + w6*a31 + w7*a32 + w8*a33;

        acc00 = fmaf(pwc, s00, acc00);
        acc01 = fmaf(pwc, s01, acc01);
        acc10 = fmaf(pwc, s10, acc10);
        acc11 = fmaf(pwc, s11, acc11);

        __syncthreads();                 // next plane ready; readers of curp done
    }

    float* outp = g_partial + (size_t)(chunk * NIMG + img) * NPIX;
    outp[ py      * 32 + px    ] = acc00;
    outp[ py      * 32 + px + 1] = acc01;
    outp[(py + 1) * 32 + px    ] = acc10;
    outp[(py + 1) * 32 + px + 1] = acc11;
}

// ---------------------------------------------------------------------------
// Kernel B: deterministic chunk reduce, single-pass top-20 via per-warp
//           bitonic sort + candidate rank counting (exact JAX tie order),
//           ballot prefix for unselected, invperm gather, float32 outputs.
// ---------------------------------------------------------------------------
__global__ __launch_bounds__(1024)
void patch_vote_kB(float* __restrict__ out) {
    int tid  = threadIdx.x;
    int img  = blockIdx.x;
    int lane = tid & 31, warp = tid >> 5;

    __shared__ unsigned long long scand[32 * KTOP];  // per-warp sorted top-20
    __shared__ int s_invp[NUNSEL];
    __shared__ int s_flag[NPIX];
    __shared__ int warpcnt[32];

    if (tid < NUNSEL) s_invp[tid] = g_invperm[tid];
    s_flag[tid] = 0;

    // deterministic chunk reduction (bias is a constant shift: order-invariant)
    float val = 0.f;
    const float* pp = g_partial + (size_t)img * NPIX + tid;
#pragma unroll
    for (int c = 0; c < NCHUNK; c++) val += pp[(size_t)c * NIMG * NPIX];

    // orderable key: (monotone float bits : 1023 - pix) -> max == JAX order
    uint32_t fb = __float_as_uint(val);
    fb = (fb & 0x80000000u) ? ~fb : (fb | 0x80000000u);
    unsigned long long key =
        ((unsigned long long)fb << 32) | (uint32_t)(NPIX - 1 - tid);

    // per-warp bitonic sort, DESCENDING (lane 0 = max). Keys are unique.
#pragma unroll
    for (int k = 2; k <= 32; k <<= 1) {
#pragma unroll
        for (int j = k >> 1; j > 0; j >>= 1) {
            unsigned long long o = __shfl_xor_sync(0xffffffffu, key, j);
            bool dirAsc  = ((lane & k) != 0);        // inverted -> descending
            bool isLower = ((lane & j) == 0);
            bool takeMin = (dirAsc == isLower);
            key = takeMin ? (key < o ? key : o) : (key > o ? key : o);
        }
    }
    if (lane < KTOP) scand[warp * KTOP + lane] = key;
    __syncthreads();

    // exact global rank for each of the 640 candidates
    if (tid < 32 * KTOP) {
        unsigned long long c = scand[tid];
        int grank = 0;
#pragma unroll 4
        for (int w = 0; w < 32; w++) {
            const unsigned long long* sl = scand + w * KTOP;
            int lo = 0, hi = KTOP;
            while (lo < hi) {                 // count of entries > c
                int mid = (lo + hi) >> 1;
                if (sl[mid] > c) lo = mid + 1; else hi = mid;
            }
            grank += lo;
        }
        if (grank < KTOP) {
            int pix = NPIX - 1 - (int)(uint32_t)(c & 0xffffffffu);
            int X = pix & 31, Y = pix >> 5;
            float xo = (float)(X < 1 ? 1 : X);
            float yo = (float)(Y < 1 ? 1 : Y);
            out[              img * PTOT + grank] = xo;   // x block
            out[NIMG * PTOT + img * PTOT + grank] = yo;   // y block
            s_flag[pix] = 1;
        }
    }
    __syncthreads();

    // unselected positions via ballot prefix, gather through invperm
    bool sel = (s_flag[tid] != 0);
    unsigned bal = __ballot_sync(0xffffffffu, sel);
    if (lane == 0) warpcnt[warp] = __popc(bal);
    __syncthreads();
    int before = __popc(bal & ((1u << lane) - 1u));
    for (int w2 = 0; w2 < warp; w2++) before += warpcnt[w2];

    if (!sel) {
        int u = tid - before;           // position among unselected (0..1003)
        int j = s_invp[u];
        if (j >= 0) {
            int X = tid & 31, Y = tid >> 5;
            float xo = (float)(X < 1 ? 1 : X);
            float yo = (float)(Y < 1 ? 1 : Y);
            out[              img * PTOT + KTOP + j] = xo;
            out[NIMG * PTOT + img * PTOT + KTOP + j] = yo;
        }
    }
}

extern "C" void kernel_launch(void* const* d_in, const int* in_sizes, int n_in,
                              void* d_out, int out_size) {
    const float* feature = (const float*)d_in[0];
    const float* dww     = (const float*)d_in[1];
    const float* pww     = (const float*)d_in[3];
    float* out = (float*)d_out;

    patch_vote_kA<<<NPERMBLK + NCHUNK * NIMG, 256>>>(feature, dww, pww);
    patch_vote_kB<<<NIMG, 1024>>>(out);
}

// round 4
// speedup vs baseline: 1.2101x; 1.1760x over previous
#include <cuda_runtime.h>
#include <cstdint>

// Problem constants
#define CCH    384
#define NPIX   1024          // 32*32
#define NIMG   16            // only first n=16 rows matter
#define KTOP   20
#define PTOT   96
#define NREM   76            // P - K
#define NUNSEL 1004          // 1024 - 20
#define NCHUNK 16
#define CHPER  24            // 384 / 16
#define NBATCH 6             // 24 channels / 4 per batch
#define NPERMBLK 16
#define ELEM_PER_PB 63       // 16*63 = 1008 >= 1004
#define PLROW  34
#define PLSZ   (34 * 34)

// Scratch (device globals: no allocation allowed)
__device__ float g_partial[NCHUNK * NIMG * NPIX];   // [chunk][img][pix]
__device__ int   g_invperm[NUNSEL];

__device__ __forceinline__ uint32_t rotl32(uint32_t x, int d) {
    return (x << d) | (x >> (32 - d));
}

// Threefry-2x32, 20 rounds (matches JAX threefry2x32_p)
__device__ __forceinline__ void threefry2x32(uint32_t k0, uint32_t k1,
                                             uint32_t x0, uint32_t x1,
                                             uint32_t& o0, uint32_t& o1) {
    uint32_t k2 = k0 ^ k1 ^ 0x1BD11BDAu;
#define TF_RND(r) { x0 += x1; x1 = rotl32(x1, (r)); x1 ^= x0; }
    x0 += k0; x1 += k1;
    TF_RND(13) TF_RND(15) TF_RND(26) TF_RND(6)
    x0 += k1; x1 += k2 + 1u;
    TF_RND(17) TF_RND(29) TF_RND(16) TF_RND(24)
    x0 += k2; x1 += k0 + 2u;
    TF_RND(13) TF_RND(15) TF_RND(26) TF_RND(6)
    x0 += k0; x1 += k1 + 3u;
    TF_RND(17) TF_RND(29) TF_RND(16) TF_RND(24)
    x0 += k1; x1 += k2 + 4u;
    TF_RND(13) TF_RND(15) TF_RND(26) TF_RND(6)
    x0 += k2; x1 += k0 + 5u;
#undef TF_RND
    o0 = x0; o1 = x1;
}

// ---------------------------------------------------------------------------
// Kernel A: blocks [0, NPERMBLK): JAX permutation inverse map;
//           blocks [NPERMBLK, NPERMBLK+256): fused depthwise-3x3 + pointwise
//           partial sums. 24 channels/block, batches of 4 with double-buffered
//           smem planes, batched prefetch (MLP=4/thread), 1 barrier per batch.
// ---------------------------------------------------------------------------
__global__ __launch_bounds__(256)
void patch_vote_kA(const float* __restrict__ feature,
                   const float* __restrict__ dww,
                   const float* __restrict__ pww) {
    int tid = threadIdx.x;

    if (blockIdx.x < NPERMBLK) {
        // ---- permutation block (verified exact) ----
        __shared__ __align__(16) uint32_t bits[NUNSEL];   // 1004 = 251 * 4
        uint32_t s0, s1;
        threefry2x32(0u, 42u, 0u, 1u, s0, s1);
        for (int i = tid; i < NUNSEL; i += 256) {
            uint32_t b1, b2;
            threefry2x32(s0, s1, 0u, (uint32_t)i, b1, b2);
            bits[i] = b1 ^ b2;
        }
        __syncthreads();

        int e = tid >> 2, part = tid & 3;
        int idx = blockIdx.x * ELEM_PER_PB + e;
        int rank = 0;
        bool valid = (e < ELEM_PER_PB) && (idx < NUNSEL);
        if (valid) {
            uint32_t bi = bits[idx];
            int q4b = part * 63;
            int q4e = q4b + 63; if (q4e > 251) q4e = 251;
            const uint4* b4 = reinterpret_cast<const uint4*>(bits);
            for (int q4 = q4b; q4 < q4e; q4++) {
                uint4 v = b4[q4];
                int q = q4 * 4;
                rank += (v.x < bi) || (v.x == bi && (q    ) < idx);
                rank += (v.y < bi) || (v.y == bi && (q + 1) < idx);
                rank += (v.z < bi) || (v.z == bi && (q + 2) < idx);
                rank += (v.w < bi) || (v.w == bi && (q + 3) < idx);
            }
        }
        rank += __shfl_xor_sync(0xffffffffu, rank, 1);
        rank += __shfl_xor_sync(0xffffffffu, rank, 2);
        if (valid && part == 0)
            g_invperm[idx] = (rank < NREM) ? rank : -1;
        return;
    }

    // ---- conv block ----
    int id    = blockIdx.x - NPERMBLK;
    int img   = id >> 4;          // / NCHUNK
    int chunk = id & 15;
    int c0    = chunk * CHPER;

    __shared__ float planes[2][4][PLSZ];
    __shared__ float wsm[CHPER * 10];

    for (int i = tid; i < 2 * 4 * PLSZ; i += 256)
        (&planes[0][0][0])[i] = 0.f;
    for (int i = tid; i < CHPER * 10; i += 256) {
        int ch = i / 10, k = i - ch * 10;
        wsm[i] = (k < 9) ? __ldg(dww + (size_t)(c0 + ch) * 9 + k)
                         : __ldg(pww + c0 + ch);
    }

    // 2x2 output tile per thread
    int tx = tid & 15, ty = tid >> 4;
    int px = tx * 2, py = ty * 2;

    // float4 load -> smem mapping
    int lp = tid * 4;
    int ly = lp >> 5, lx = lp & 31;
    int dstoff = (ly + 1) * PLROW + lx + 1;

    const float4* f4 = reinterpret_cast<const float4*>(
        feature + ((size_t)img * CCH + c0) * NPIX);

    float4 v0, v1, v2, v3;
    // batch 0 (channels 0..3) — 4 loads in flight
    v0 = f4[0 * 256 + tid]; v1 = f4[1 * 256 + tid];
    v2 = f4[2 * 256 + tid]; v3 = f4[3 * 256 + tid];
    __syncthreads();            // zero-init + weights complete
    {
        float* d;
        d = &planes[0][0][dstoff]; d[0]=v0.x; d[1]=v0.y; d[2]=v0.z; d[3]=v0.w;
        d = &planes[0][1][dstoff]; d[0]=v1.x; d[1]=v1.y; d[2]=v1.z; d[3]=v1.w;
        d = &planes[0][2][dstoff]; d[0]=v2.x; d[1]=v2.y; d[2]=v2.z; d[3]=v2.w;
        d = &planes[0][3][dstoff]; d[0]=v3.x; d[1]=v3.y; d[2]=v3.z; d[3]=v3.w;
    }
    // batch 1 prefetch (channels 4..7)
    v0 = f4[4 * 256 + tid]; v1 = f4[5 * 256 + tid];
    v2 = f4[6 * 256 + tid]; v3 = f4[7 * 256 + tid];
    __syncthreads();            // buffer 0 visible to all

    float acc00 = 0.f, acc01 = 0.f, acc10 = 0.f, acc11 = 0.f;

#pragma unroll
    for (int b = 0; b < NBATCH; b++) {
        int cur = b & 1;
        if (b + 1 < NBATCH) {   // store prefetched batch b+1 into other buffer
            float* d;
            d = &planes[cur^1][0][dstoff]; d[0]=v0.x; d[1]=v0.y; d[2]=v0.z; d[3]=v0.w;
            d = &planes[cur^1][1][dstoff]; d[0]=v1.x; d[1]=v1.y; d[2]=v1.z; d[3]=v1.w;
            d = &planes[cur^1][2][dstoff]; d[0]=v2.x; d[1]=v2.y; d[2]=v2.z; d[3]=v2.w;
            d = &planes[cur^1][3][dstoff]; d[0]=v3.x; d[1]=v3.y; d[2]=v3.z; d[3]=v3.w;
        }
        if (b + 2 < NBATCH) {   // prefetch batch b+2 (4 independent LDG.128)
            int cb = (b + 2) * 4;
            v0 = f4[(cb + 0) * 256 + tid]; v1 = f4[(cb + 1) * 256 + tid];
            v2 = f4[(cb + 2) * 256 + tid]; v3 = f4[(cb + 3) * 256 + tid];
        }

#pragma unroll
        for (int j = 0; j < 4; j++) {
            const float* wp = wsm + (b * 4 + j) * 10;
            float w0 = wp[0], w1 = wp[1], w2 = wp[2];
            float w3 = wp[3], w4 = wp[4], w5 = wp[5];
            float w6 = wp[6], w7 = wp[7], w8 = wp[8];
            float pwc = wp[9];

            const float* pr = &planes[cur][j][py * PLROW + px];
            float a00 = pr[0],   a01 = pr[1],   a02 = pr[2],   a03 = pr[3];
            float a10 = pr[34],  a11 = pr[35],  a12 = pr[36],  a13 = pr[37];
            float a20 = pr[68],  a21 = pr[69],  a22 = pr[70],  a23 = pr[71];
            float a30 = pr[102], a31 = pr[103], a32 = pr[104], a33 = pr[105];

            float s00 = w0*a00 + w1*a01 + w2*a02
                      + w3*a10 + w4*a11 + w5*a12
                      + w6*a20 + w7*a21 + w8*a22;
            float s01 = w0*a01 + w1*a02 + w2*a03
                      + w3*a11 + w4*a12 + w5*a13
                      + w6*a21 + w7*a22 + w8*a23;
            float s10 = w0*a10 + w1*a11 + w2*a12
                      + w3*a20 + w4*a21 + w5*a22
                      + w6*a30 + w7*a31 + w8*a32;
            float s11 = w0*a11 + w1*a12 + w2*a13
                      + w3*a21 + w4*a22 + w5*a23
                      + w6*a31 + w7*a32 + w8*a33;

            acc00 = fmaf(pwc, s00, acc00);
            acc01 = fmaf(pwc, s01, acc01);
            acc10 = fmaf(pwc, s10, acc10);
            acc11 = fmaf(pwc, s11, acc11);
        }
        __syncthreads();        // everyone done with planes[cur] & stores
    }

    float* outp = g_partial + (size_t)(chunk * NIMG + img) * NPIX;
    outp[ py      * 32 + px    ] = acc00;
    outp[ py      * 32 + px + 1] = acc01;
    outp[(py + 1) * 32 + px    ] = acc10;
    outp[(py + 1) * 32 + px + 1] = acc11;
}

// ---------------------------------------------------------------------------
// Kernel B: MLP chunk reduce, per-warp bitonic sort, threshold-gated exact
//           rank counting (branchless 5-step over padded 32-lists), ballot
//           prefix for unselected, invperm gather, float32 outputs.
// ---------------------------------------------------------------------------
__global__ __launch_bounds__(1024)
void patch_vote_kB(float* __restrict__ out) {
    int tid  = threadIdx.x;
    int img  = blockIdx.x;
    int lane = tid & 31, warp = tid >> 5;

    __shared__ unsigned long long scand[32 * 32];   // padded per-warp lists
    __shared__ unsigned long long s_S;
    __shared__ int s_invp[NUNSEL];
    __shared__ int s_flag[NPIX];
    __shared__ int warpcnt[32];

    if (tid < NUNSEL) s_invp[tid] = g_invperm[tid];
    s_flag[tid] = 0;

    // chunk reduction, 4 independent accumulator chains (MLP)
    const float* pp = g_partial + (size_t)img * NPIX + tid;
    float r0 = 0.f, r1 = 0.f, r2 = 0.f, r3 = 0.f;
#pragma unroll
    for (int c = 0; c < NCHUNK; c += 4) {
        r0 += __ldg(pp + (size_t)(c + 0) * NIMG * NPIX);
        r1 += __ldg(pp + (size_t)(c + 1) * NIMG * NPIX);
        r2 += __ldg(pp + (size_t)(c + 2) * NIMG * NPIX);
        r3 += __ldg(pp + (size_t)(c + 3) * NIMG * NPIX);
    }
    float val = (r0 + r1) + (r2 + r3);

    // orderable key: (monotone float bits : 1023 - pix) -> max == JAX order
    uint32_t fb = __float_as_uint(val);
    fb = (fb & 0x80000000u) ? ~fb : (fb | 0x80000000u);
    unsigned long long key =
        ((unsigned long long)fb << 32) | (uint32_t)(NPIX - 1 - tid);

    // per-warp bitonic sort, DESCENDING (lane 0 = max). Keys unique.
#pragma unroll
    for (int k = 2; k <= 32; k <<= 1) {
#pragma unroll
        for (int j = k >> 1; j > 0; j >>= 1) {
            unsigned long long o = __shfl_xor_sync(0xffffffffu, key, j);
            bool dirAsc  = ((lane & k) != 0);
            bool isLower = ((lane & j) == 0);
            bool takeMin = (dirAsc == isLower);
            key = takeMin ? (key < o ? key : o) : (key > o ? key : o);
        }
    }
    scand[(warp << 5) + lane] = (lane < KTOP) ? key : 0ull;  // pad with 0
    __syncthreads();

    // lower-bound threshold S = max over warps of (warp's 20th key) <= K20
    if (warp == 0) {
        unsigned long long t = scand[(lane << 5) + (KTOP - 1)];
#pragma unroll
        for (int off = 16; off; off >>= 1) {
            unsigned long long o = __shfl_xor_sync(0xffffffffu, t, off);
            if (o > t) t = o;
        }
        if (lane == 0) s_S = t;
    }
    __syncthreads();

    // exact rank for few candidates (key >= S guarantees top-20 coverage)
    if (lane < KTOP && key >= s_S) {
        int grank = 0;
#pragma unroll 4
        for (int w = 0; w < 32; w++) {
            const unsigned long long* sl = scand + (w << 5);
            int p = 0;                         // count of entries > key
            p += (sl[p + 15] > key) ? 16 : 0;
            p += (sl[p + 7]  > key) ? 8  : 0;
            p += (sl[p + 3]  > key) ? 4  : 0;
            p += (sl[p + 1]  > key) ? 2  : 0;
            p += (sl[p]      > key) ? 1  : 0;
            grank += p;
        }
        if (grank < KTOP) {
            int pix = NPIX - 1 - (int)(uint32_t)(key & 0xffffffffu);
            int X = pix & 31, Y = pix >> 5;
            float xo = (float)(X < 1 ? 1 : X);
            float yo = (float)(Y < 1 ? 1 : Y);
            out[              img * PTOT + grank] = xo;
            out[NIMG * PTOT + img * PTOT + grank] = yo;
            s_flag[pix] = 1;
        }
    }
    __syncthreads();

    // unselected positions via ballot prefix, gather through invperm
    bool sel = (s_flag[tid] != 0);
    unsigned bal = __ballot_sync(0xffffffffu, sel);
    if (lane == 0) warpcnt[warp] = __popc(bal);
    __syncthreads();
    int before = __popc(bal & ((1u << lane) - 1u));
    for (int w2 = 0; w2 < warp; w2++) before += warpcnt[w2];

    if (!sel) {
        int u = tid - before;           // position among unselected (0..1003)
        int j = s_invp[u];
        if (j >= 0) {
            int X = tid & 31, Y = tid >> 5;
            float xo = (float)(X < 1 ? 1 : X);
            float yo = (float)(Y < 1 ? 1 : Y);
            out[              img * PTOT + KTOP + j] = xo;
            out[NIMG * PTOT + img * PTOT + KTOP + j] = yo;
        }
    }
}

extern "C" void kernel_launch(void* const* d_in, const int* in_sizes, int n_in,
                              void* d_out, int out_size) {
    const float* feature = (const float*)d_in[0];
    const float* dww     = (const float*)d_in[1];
    const float* pww     = (const float*)d_in[3];
    float* out = (float*)d_out;

    patch_vote_kA<<<NPERMBLK + NCHUNK * NIMG, 256>>>(feature, dww, pww);
    patch_vote_kB<<<NIMG, 1024>>>(out);
}